// round 1
// baseline (speedup 1.0000x reference)
#include <cuda_runtime.h>
#include <cstdint>

// ---------------- problem constants (fixed by the reference) ----------------
#define BS      8
#define NQ      900
#define EMBED   256
#define HEADS   8
#define HEAD_DIM 32
#define LEVELS  4
#define POINTS  4
#define NV      13294          // 100*100 + 50*50 + 25*25 + 13*13
#define NBQ     (BS * NQ)      // 7200

__device__ __constant__ int c_LH[4] = {100, 50, 25, 13};
__device__ __constant__ int c_LW[4] = {100, 50, 25, 13};
__device__ __constant__ int c_LS[4] = {0, 10000, 12500, 13125};

// ---------------- scratch (static device allocations, allowed) --------------
__device__ float g_v[(size_t)BS * NV * EMBED];     // projected value, ~109 MB
__device__ float g_off[(size_t)NBQ * 256];         // sampling offsets raw
__device__ float g_aw[(size_t)NBQ * 128];          // attention logits
__device__ float g_attn[(size_t)NBQ * EMBED];      // attention output pre-Wout

// ---------------- generic fp32 tiled GEMM: C = A(MxK) * B(KxN) + bias (+resid)
#define BM 64
#define BN 64
#define BK 16

__global__ __launch_bounds__(256)
void gemm_bias_kernel(const float* __restrict__ A, const float* __restrict__ B,
                      const float* __restrict__ bias, const float* __restrict__ resid,
                      float* __restrict__ C, int M, int N, int K, int addResid)
{
    __shared__ float As[BK][BM + 4];
    __shared__ float Bs[BK][BN];

    const int tid = threadIdx.x;              // 256 threads
    const int m0 = blockIdx.y * BM;
    const int n0 = blockIdx.x * BN;
    const int tr = tid >> 4;                  // 0..15
    const int tc = tid & 15;                  // 0..15

    // load indices
    const int am = tid >> 2;                  // 0..63 (row within A tile)
    const int ak = (tid & 3) * 4;             // 0,4,8,12
    const int bk = tid >> 4;                  // 0..15 (row within B tile)
    const int bn = (tid & 15) * 4;            // 0..60

    float acc[4][4];
#pragma unroll
    for (int i = 0; i < 4; i++)
#pragma unroll
        for (int j = 0; j < 4; j++) acc[i][j] = 0.f;

    for (int k0 = 0; k0 < K; k0 += BK) {
        float4 av;
        if (m0 + am < M)
            av = *reinterpret_cast<const float4*>(&A[(size_t)(m0 + am) * K + k0 + ak]);
        else
            av = make_float4(0.f, 0.f, 0.f, 0.f);
        As[ak + 0][am] = av.x;
        As[ak + 1][am] = av.y;
        As[ak + 2][am] = av.z;
        As[ak + 3][am] = av.w;

        float4 bv = *reinterpret_cast<const float4*>(&B[(size_t)(k0 + bk) * N + n0 + bn]);
        *reinterpret_cast<float4*>(&Bs[bk][bn]) = bv;

        __syncthreads();

#pragma unroll
        for (int k = 0; k < BK; k++) {
            float4 a = *reinterpret_cast<const float4*>(&As[k][tr * 4]);
            float4 b = *reinterpret_cast<const float4*>(&Bs[k][tc * 4]);
            float ar[4] = {a.x, a.y, a.z, a.w};
            float br[4] = {b.x, b.y, b.z, b.w};
#pragma unroll
            for (int i = 0; i < 4; i++)
#pragma unroll
                for (int j = 0; j < 4; j++)
                    acc[i][j] = fmaf(ar[i], br[j], acc[i][j]);
        }
        __syncthreads();
    }

#pragma unroll
    for (int i = 0; i < 4; i++) {
        int m = m0 + tr * 4 + i;
        if (m >= M) continue;
#pragma unroll
        for (int j = 0; j < 4; j++) {
            int n = n0 + tc * 4 + j;
            float v = acc[i][j] + bias[n];
            if (addResid) v += resid[(size_t)m * N + n];
            C[(size_t)m * N + n] = v;
        }
    }
}

// ---------------- sampling kernel: softmax + bilinear gather ----------------
__global__ __launch_bounds__(256)
void msda_sample_kernel(const float* __restrict__ rp)
{
    const int bq = blockIdx.x;          // 0..NBQ-1
    const int b = bq / NQ;
    const int tid = threadIdx.x;

    __shared__ float s_aw[128];
    __shared__ int   s_pos[128][4];
    __shared__ float s_wt[128][4];

    if (tid < 128) s_aw[tid] = g_aw[(size_t)bq * 128 + tid];
    __syncthreads();

    // per-head softmax over 16 (levels*points)
    if (tid < HEADS) {
        const int base = tid * 16;
        float mx = -1e30f;
#pragma unroll
        for (int i = 0; i < 16; i++) mx = fmaxf(mx, s_aw[base + i]);
        float e[16];
        float sum = 0.f;
#pragma unroll
        for (int i = 0; i < 16; i++) { e[i] = __expf(s_aw[base + i] - mx); sum += e[i]; }
        float inv = 1.f / sum;
#pragma unroll
        for (int i = 0; i < 16; i++) s_aw[base + i] = e[i] * inv;
    }
    __syncthreads();

    // per-sample corner weights/indices (128 samples = heads*levels*points)
    if (tid < 128) {
        const int s = tid;
        const int l = (s >> 2) & 3;
        const float aw = s_aw[s];
        const float offx = g_off[(size_t)bq * 256 + s * 2];
        const float offy = g_off[(size_t)bq * 256 + s * 2 + 1];
        const float rx = rp[((size_t)bq * LEVELS + l) * 2];
        const float ry = rp[((size_t)bq * LEVELS + l) * 2 + 1];
        const int W = c_LW[l], H = c_LH[l], st = c_LS[l];

        const float locx = rx + offx / (float)W;
        const float locy = ry + offy / (float)H;
        const float x = locx * (float)W - 0.5f;
        const float y = locy * (float)H - 0.5f;
        const float x0f = floorf(x), y0f = floorf(y);
        const float lx = x - x0f, ly = y - y0f;
        const int x0 = (int)x0f, y0 = (int)y0f;

#pragma unroll
        for (int c = 0; c < 4; c++) {
            const int dx = c & 1, dy = c >> 1;
            const int xi = x0 + dx, yi = y0 + dy;
            const float wx = dx ? lx : (1.f - lx);
            const float wy = dy ? ly : (1.f - ly);
            const bool valid = (xi >= 0) && (xi < W) && (yi >= 0) && (yi < H);
            const int xc = min(max(xi, 0), W - 1);
            const int yc = min(max(yi, 0), H - 1);
            s_pos[s][c] = st + yc * W + xc;
            s_wt[s][c] = valid ? (wx * wy * aw) : 0.f;
        }
    }
    __syncthreads();

    // accumulate: thread (h, d) — each warp covers one head, coalesced 128B loads
    const int h = tid >> 5;
    const float* vb = g_v + (size_t)b * NV * EMBED + tid;   // tid = h*32+d column
    float acc = 0.f;
#pragma unroll
    for (int i = 0; i < 16; i++) {
        const int s = h * 16 + i;
#pragma unroll
        for (int c = 0; c < 4; c++) {
            acc = fmaf(s_wt[s][c], __ldg(vb + (size_t)s_pos[s][c] * EMBED), acc);
        }
    }
    g_attn[(size_t)bq * EMBED + tid] = acc;
}

// ---------------- launch --------------------------------------------------
extern "C" void kernel_launch(void* const* d_in, const int* in_sizes, int n_in,
                              void* d_out, int out_size)
{
    const float* query  = (const float*)d_in[0];
    const float* value  = (const float*)d_in[1];
    const float* rp     = (const float*)d_in[2];
    // d_in[3] = spatial_shapes (int32) — compile-time constants here
    const float* W_off  = (const float*)d_in[4];
    const float* b_off  = (const float*)d_in[5];
    const float* W_attn = (const float*)d_in[6];
    const float* b_attn = (const float*)d_in[7];
    const float* W_v    = (const float*)d_in[8];
    const float* b_v    = (const float*)d_in[9];
    const float* W_out  = (const float*)d_in[10];
    const float* b_out  = (const float*)d_in[11];
    float* out = (float*)d_out;

    float *pv, *poff, *paw, *pattn;
    cudaGetSymbolAddress((void**)&pv,    g_v);
    cudaGetSymbolAddress((void**)&poff,  g_off);
    cudaGetSymbolAddress((void**)&paw,   g_aw);
    cudaGetSymbolAddress((void**)&pattn, g_attn);

    // 1) value projection: (BS*NV, 256) @ (256, 256) + b_v
    {
        const int M = BS * NV;
        dim3 grid(EMBED / BN, (M + BM - 1) / BM);
        gemm_bias_kernel<<<grid, 256>>>(value, W_v, b_v, nullptr, pv, M, EMBED, EMBED, 0);
    }
    // 2) offsets: (NBQ, 256) @ (256, 256) + b_off
    {
        dim3 grid(256 / BN, (NBQ + BM - 1) / BM);
        gemm_bias_kernel<<<grid, 256>>>(query, W_off, b_off, nullptr, poff, NBQ, 256, EMBED, 0);
    }
    // 3) attention logits: (NBQ, 256) @ (256, 128) + b_attn
    {
        dim3 grid(128 / BN, (NBQ + BM - 1) / BM);
        gemm_bias_kernel<<<grid, 256>>>(query, W_attn, b_attn, nullptr, paw, NBQ, 128, EMBED, 0);
    }
    // 4) softmax + bilinear sampling
    msda_sample_kernel<<<NBQ, 256>>>(rp);

    // 5) output projection + residual: (NBQ,256) @ (256,256) + b_out + query
    {
        dim3 grid(EMBED / BN, (NBQ + BM - 1) / BM);
        gemm_bias_kernel<<<grid, 256>>>(pattn, W_out, b_out, query, out, NBQ, EMBED, EMBED, 1);
    }
}

// round 2
// speedup vs baseline: 1.0266x; 1.0266x over previous
#include <cuda_runtime.h>
#include <cstdint>

// ---------------- problem constants (fixed by the reference) ----------------
#define BS      8
#define NQ      900
#define EMBED   256
#define HEADS   8
#define HEAD_DIM 32
#define LEVELS  4
#define POINTS  4
#define NV      13294          // 100*100 + 50*50 + 25*25 + 13*13
#define NBQ     (BS * NQ)      // 7200

__device__ __constant__ int c_LH[4] = {100, 50, 25, 13};
__device__ __constant__ int c_LW[4] = {100, 50, 25, 13};
__device__ __constant__ int c_LS[4] = {0, 10000, 12500, 13125};

// ---------------- scratch (static device allocations, allowed) --------------
__device__ float g_v[(size_t)BS * NV * EMBED];     // projected value, ~109 MB
__device__ float g_off[(size_t)NBQ * 256];         // sampling offsets raw
__device__ float g_aw[(size_t)NBQ * 128];          // attention logits
__device__ float g_attn[(size_t)NBQ * EMBED];      // attention output pre-Wout

// ---------------- f32x2 helpers ---------------------------------------------
__device__ __forceinline__ unsigned long long pack2(float x, float y) {
    unsigned long long r;
    asm("mov.b64 %0, {%1, %2};" : "=l"(r) : "f"(x), "f"(y));
    return r;
}
__device__ __forceinline__ void fma2(unsigned long long& d,
                                     unsigned long long a,
                                     unsigned long long b) {
    asm("fma.rn.f32x2 %0, %1, %2, %0;" : "+l"(d) : "l"(a), "l"(b));
}

// ---------------- fp32 tiled GEMM (128x128x16, 8x8/thread, f32x2 FMA) -------
// C = A(MxK) * B(KxN) + bias (+ resid).  N must be a multiple of 128.
#define BM 128
#define BN 128
#define BK 16

__global__ __launch_bounds__(256, 2)
void gemm_bias_kernel(const float* __restrict__ A, const float* __restrict__ B,
                      const float* __restrict__ bias, const float* __restrict__ resid,
                      float* __restrict__ C, int M, int N, int K, int addResid)
{
    __shared__ float As[2][BK][BM + 4];   // transposed A tile: As[k][m]
    __shared__ float Bs[2][BK][BN];       // Bs[k][n]

    const int tid = threadIdx.x;          // 256 threads
    const int m0 = blockIdx.y * BM;
    const int n0 = blockIdx.x * BN;

    // output micro-tile 8x8
    const int tr = (tid >> 4) * 8;        // 0..120
    const int tc = (tid & 15) * 8;        // 0..120

    // A load: 512 float4/tile, 2 per thread. idx -> row=idx>>2, kq=(idx&3)*4
    const int a_row0 = tid >> 2;          // idx = tid
    const int a_kq   = (tid & 3) * 4;
    const int a_row1 = a_row0 + 64;       // idx = tid + 256

    // B load: 512 float4/tile, 2 per thread. idx -> krow=idx>>5, col=(idx&31)*4
    const int b_k0  = tid >> 5;           // 0..7
    const int b_col = (tid & 31) * 4;
    const int b_k1  = b_k0 + 8;

    unsigned long long acc[8][4];
#pragma unroll
    for (int i = 0; i < 8; i++)
#pragma unroll
        for (int j = 0; j < 4; j++) acc[i][j] = 0ull;

    const int ntiles = K / BK;

    // --- prologue: load tile 0 straight into smem buf 0 ---
    {
        float4 av0 = make_float4(0.f, 0.f, 0.f, 0.f), av1 = av0;
        if (m0 + a_row0 < M) av0 = *reinterpret_cast<const float4*>(&A[(size_t)(m0 + a_row0) * K + a_kq]);
        if (m0 + a_row1 < M) av1 = *reinterpret_cast<const float4*>(&A[(size_t)(m0 + a_row1) * K + a_kq]);
        As[0][a_kq + 0][a_row0] = av0.x; As[0][a_kq + 1][a_row0] = av0.y;
        As[0][a_kq + 2][a_row0] = av0.z; As[0][a_kq + 3][a_row0] = av0.w;
        As[0][a_kq + 0][a_row1] = av1.x; As[0][a_kq + 1][a_row1] = av1.y;
        As[0][a_kq + 2][a_row1] = av1.z; As[0][a_kq + 3][a_row1] = av1.w;
        *reinterpret_cast<float4*>(&Bs[0][b_k0][b_col]) =
            *reinterpret_cast<const float4*>(&B[(size_t)b_k0 * N + n0 + b_col]);
        *reinterpret_cast<float4*>(&Bs[0][b_k1][b_col]) =
            *reinterpret_cast<const float4*>(&B[(size_t)b_k1 * N + n0 + b_col]);
    }
    __syncthreads();

    int buf = 0;
    for (int kt = 0; kt < ntiles; kt++) {
        // stage next tile into registers
        float4 av0, av1, bv0, bv1;
        const bool more = (kt + 1 < ntiles);
        if (more) {
            const int kb = (kt + 1) * BK;
            av0 = make_float4(0.f, 0.f, 0.f, 0.f); av1 = av0;
            if (m0 + a_row0 < M) av0 = *reinterpret_cast<const float4*>(&A[(size_t)(m0 + a_row0) * K + kb + a_kq]);
            if (m0 + a_row1 < M) av1 = *reinterpret_cast<const float4*>(&A[(size_t)(m0 + a_row1) * K + kb + a_kq]);
            bv0 = *reinterpret_cast<const float4*>(&B[(size_t)(kb + b_k0) * N + n0 + b_col]);
            bv1 = *reinterpret_cast<const float4*>(&B[(size_t)(kb + b_k1) * N + n0 + b_col]);
        }

        // compute on current buffer
#pragma unroll
        for (int k = 0; k < BK; k++) {
            float4 a0 = *reinterpret_cast<const float4*>(&As[buf][k][tr]);
            float4 a1 = *reinterpret_cast<const float4*>(&As[buf][k][tr + 4]);
            ulonglong2 bA = *reinterpret_cast<const ulonglong2*>(&Bs[buf][k][tc]);
            ulonglong2 bB = *reinterpret_cast<const ulonglong2*>(&Bs[buf][k][tc + 4]);
            unsigned long long bb[4] = {bA.x, bA.y, bB.x, bB.y};
            float a[8] = {a0.x, a0.y, a0.z, a0.w, a1.x, a1.y, a1.z, a1.w};
#pragma unroll
            for (int i = 0; i < 8; i++) {
                unsigned long long ai = pack2(a[i], a[i]);
#pragma unroll
                for (int j = 0; j < 4; j++) fma2(acc[i][j], ai, bb[j]);
            }
        }

        if (more) {
            const int nb = buf ^ 1;
            As[nb][a_kq + 0][a_row0] = av0.x; As[nb][a_kq + 1][a_row0] = av0.y;
            As[nb][a_kq + 2][a_row0] = av0.z; As[nb][a_kq + 3][a_row0] = av0.w;
            As[nb][a_kq + 0][a_row1] = av1.x; As[nb][a_kq + 1][a_row1] = av1.y;
            As[nb][a_kq + 2][a_row1] = av1.z; As[nb][a_kq + 3][a_row1] = av1.w;
            *reinterpret_cast<float4*>(&Bs[nb][b_k0][b_col]) = bv0;
            *reinterpret_cast<float4*>(&Bs[nb][b_k1][b_col]) = bv1;
            __syncthreads();
            buf = nb;
        }
    }

    // --- epilogue ---
    float4 bias0 = *reinterpret_cast<const float4*>(&bias[n0 + tc]);
    float4 bias1 = *reinterpret_cast<const float4*>(&bias[n0 + tc + 4]);
    const float bb[8] = {bias0.x, bias0.y, bias0.z, bias0.w,
                         bias1.x, bias1.y, bias1.z, bias1.w};
#pragma unroll
    for (int i = 0; i < 8; i++) {
        const int m = m0 + tr + i;
        if (m >= M) continue;
        float v[8];
#pragma unroll
        for (int j = 0; j < 4; j++) {
            float2 f = *reinterpret_cast<float2*>(&acc[i][j]);
            v[2 * j + 0] = f.x + bb[2 * j + 0];
            v[2 * j + 1] = f.y + bb[2 * j + 1];
        }
        if (addResid) {
            float4 r0 = *reinterpret_cast<const float4*>(&resid[(size_t)m * N + n0 + tc]);
            float4 r1 = *reinterpret_cast<const float4*>(&resid[(size_t)m * N + n0 + tc + 4]);
            v[0] += r0.x; v[1] += r0.y; v[2] += r0.z; v[3] += r0.w;
            v[4] += r1.x; v[5] += r1.y; v[6] += r1.z; v[7] += r1.w;
        }
        *reinterpret_cast<float4*>(&C[(size_t)m * N + n0 + tc]) =
            make_float4(v[0], v[1], v[2], v[3]);
        *reinterpret_cast<float4*>(&C[(size_t)m * N + n0 + tc + 4]) =
            make_float4(v[4], v[5], v[6], v[7]);
    }
}

// ---------------- sampling kernel: softmax + bilinear gather ----------------
__global__ __launch_bounds__(256)
void msda_sample_kernel(const float* __restrict__ rp)
{
    const int bq = blockIdx.x;          // 0..NBQ-1
    const int b = bq / NQ;
    const int tid = threadIdx.x;

    __shared__ float s_aw[128];
    __shared__ int   s_pos[128][4];
    __shared__ float s_wt[128][4];

    if (tid < 128) s_aw[tid] = g_aw[(size_t)bq * 128 + tid];
    __syncthreads();

    // per-head softmax over 16 (levels*points)
    if (tid < HEADS) {
        const int base = tid * 16;
        float mx = -1e30f;
#pragma unroll
        for (int i = 0; i < 16; i++) mx = fmaxf(mx, s_aw[base + i]);
        float e[16];
        float sum = 0.f;
#pragma unroll
        for (int i = 0; i < 16; i++) { e[i] = __expf(s_aw[base + i] - mx); sum += e[i]; }
        float inv = 1.f / sum;
#pragma unroll
        for (int i = 0; i < 16; i++) s_aw[base + i] = e[i] * inv;
    }
    __syncthreads();

    // per-sample corner weights/indices (128 samples = heads*levels*points)
    if (tid < 128) {
        const int s = tid;
        const int l = (s >> 2) & 3;
        const float aw = s_aw[s];
        const float offx = g_off[(size_t)bq * 256 + s * 2];
        const float offy = g_off[(size_t)bq * 256 + s * 2 + 1];
        const float rx = rp[((size_t)bq * LEVELS + l) * 2];
        const float ry = rp[((size_t)bq * LEVELS + l) * 2 + 1];
        const int W = c_LW[l], H = c_LH[l], st = c_LS[l];

        const float locx = rx + offx / (float)W;
        const float locy = ry + offy / (float)H;
        const float x = locx * (float)W - 0.5f;
        const float y = locy * (float)H - 0.5f;
        const float x0f = floorf(x), y0f = floorf(y);
        const float lx = x - x0f, ly = y - y0f;
        const int x0 = (int)x0f, y0 = (int)y0f;

#pragma unroll
        for (int c = 0; c < 4; c++) {
            const int dx = c & 1, dy = c >> 1;
            const int xi = x0 + dx, yi = y0 + dy;
            const float wx = dx ? lx : (1.f - lx);
            const float wy = dy ? ly : (1.f - ly);
            const bool valid = (xi >= 0) && (xi < W) && (yi >= 0) && (yi < H);
            const int xc = min(max(xi, 0), W - 1);
            const int yc = min(max(yi, 0), H - 1);
            s_pos[s][c] = st + yc * W + xc;
            s_wt[s][c] = valid ? (wx * wy * aw) : 0.f;
        }
    }
    __syncthreads();

    // accumulate: thread (h, d) — each warp covers one head, coalesced 128B loads
    const int h = tid >> 5;
    const float* vb = g_v + (size_t)b * NV * EMBED + tid;   // tid = h*32+d column
    float acc = 0.f;
#pragma unroll
    for (int i = 0; i < 16; i++) {
        const int s = h * 16 + i;
#pragma unroll
        for (int c = 0; c < 4; c++) {
            acc = fmaf(s_wt[s][c], __ldg(vb + (size_t)s_pos[s][c] * EMBED), acc);
        }
    }
    g_attn[(size_t)bq * EMBED + tid] = acc;
}

// ---------------- launch --------------------------------------------------
extern "C" void kernel_launch(void* const* d_in, const int* in_sizes, int n_in,
                              void* d_out, int out_size)
{
    const float* query  = (const float*)d_in[0];
    const float* value  = (const float*)d_in[1];
    const float* rp     = (const float*)d_in[2];
    // d_in[3] = spatial_shapes (int32) — compile-time constants here
    const float* W_off  = (const float*)d_in[4];
    const float* b_off  = (const float*)d_in[5];
    const float* W_attn = (const float*)d_in[6];
    const float* b_attn = (const float*)d_in[7];
    const float* W_v    = (const float*)d_in[8];
    const float* b_v    = (const float*)d_in[9];
    const float* W_out  = (const float*)d_in[10];
    const float* b_out  = (const float*)d_in[11];
    float* out = (float*)d_out;

    float *pv, *poff, *paw, *pattn;
    cudaGetSymbolAddress((void**)&pv,    g_v);
    cudaGetSymbolAddress((void**)&poff,  g_off);
    cudaGetSymbolAddress((void**)&paw,   g_aw);
    cudaGetSymbolAddress((void**)&pattn, g_attn);

    // 1) value projection: (BS*NV, 256) @ (256, 256) + b_v
    {
        const int M = BS * NV;
        dim3 grid(EMBED / BN, (M + BM - 1) / BM);
        gemm_bias_kernel<<<grid, 256>>>(value, W_v, b_v, nullptr, pv, M, EMBED, EMBED, 0);
    }
    // 2) offsets: (NBQ, 256) @ (256, 256) + b_off
    {
        dim3 grid(256 / BN, (NBQ + BM - 1) / BM);
        gemm_bias_kernel<<<grid, 256>>>(query, W_off, b_off, nullptr, poff, NBQ, 256, EMBED, 0);
    }
    // 3) attention logits: (NBQ, 256) @ (256, 128) + b_attn
    {
        dim3 grid(128 / BN, (NBQ + BM - 1) / BM);
        gemm_bias_kernel<<<grid, 256>>>(query, W_attn, b_attn, nullptr, paw, NBQ, 128, EMBED, 0);
    }
    // 4) softmax + bilinear sampling
    msda_sample_kernel<<<NBQ, 256>>>(rp);

    // 5) output projection + residual: (NBQ,256) @ (256,256) + b_out + query
    {
        dim3 grid(EMBED / BN, (NBQ + BM - 1) / BM);
        gemm_bias_kernel<<<grid, 256>>>(pattn, W_out, b_out, query, out, NBQ, EMBED, EMBED, 1);
    }
}